// round 13
// baseline (speedup 1.0000x reference)
#include <cuda_runtime.h>
#include <cuda_fp16.h>
#include <cstdint>

#define NN 10000
#define MPAD 10240           // 160 * 64
#define EE 50000
#define IND 8
#define H 64
#define KH 32
#define KA 2240              // A cols: S(2048) | T(64) | h_hi(64) | h_lo(64)
#define GEPS 1e-5f
#define NORMBLKS 125         // 125 * 80 = 10000, single wave
#define CSRBLKS 125

// ===================== device scratch =====================
__device__ float g_r[2 * EE * KH];
__device__ float g_hf[NN * H];                      // fp32 node features
__device__ __half g_A[(size_t)MPAD * KA];           // GEMM A (45.9 MB)
__device__ __half g_B[2 * H * KA];                  // per-layer B as [o][c]
__device__ float g_hp[MPAD * H];                    // GEMM out: h_pre (pre-bias)
__device__ int g_ddeg[NN];
__device__ int g_soff[NN], g_cursor[NN], g_csr[EE];
__device__ int g_total;
__device__ int g_done[3];                           // [0],[1]=norm layers, [2]=csr
__device__ float g_invdeg[NN];
__device__ float g_colsum[2][H], g_colsumsq[2][H];

__device__ __forceinline__ uint32_t smem_u32(const void* p) {
    uint32_t a;
    asm("{ .reg .u64 t; cvta.to.shared.u64 t, %1; cvt.u32.u64 %0, t; }" : "=r"(a) : "l"(p));
    return a;
}
__device__ __forceinline__ void gridbar(int* ctr, int target) {
    __threadfence();
    __syncthreads();
    if (threadIdx.x == 0) {
        atomicAdd(ctr, 1);
        while (atomicAdd(ctr, 0) < target) {}
    }
    __syncthreads();
}

// ===================== setup kernels =====================
// h = x@proj_w+proj_b -> g_hf + g_A h-cols (hi/lo); zero counters
__global__ void k_proj(const float* __restrict__ x, const float* __restrict__ w,
                       const float* __restrict__ b) {
    int idx = blockIdx.x * blockDim.x + threadIdx.x;
    if (idx >= NN * H) return;
    if (idx < NN) g_ddeg[idx] = 0;
    if (idx < H) {
        g_colsum[0][idx] = 0.0f; g_colsumsq[0][idx] = 0.0f;
        g_colsum[1][idx] = 0.0f; g_colsumsq[1][idx] = 0.0f;
    }
    if (idx == 0) { g_total = 0; g_done[0] = 0; g_done[1] = 0; g_done[2] = 0; }
    int n = idx >> 6, o = idx & 63;
    float v = b[o];
#pragma unroll
    for (int i = 0; i < IND; i++) v += x[n * IND + i] * w[i * H + o];
    g_hf[idx] = v;
    __half hi = __float2half_rn(v);
    __half lo = __float2half_rn(v - __half2float(hi));
    g_A[(size_t)n * KA + 2112 + o] = hi;
    g_A[(size_t)n * KA + 2176 + o] = lo;
}
// merged: edge-MLP (both layers) + B build (both layers) + dst-degree count
#define MLPN (2 * EE * KH)
#define BTOT (2 * H * KA)
#define PREPTOT (MLPN + BTOT + EE)
__global__ void k_prep(const float* __restrict__ ea, const float* __restrict__ w1,
                       const float* __restrict__ b1, const float* __restrict__ w2,
                       const float* __restrict__ rw, const float* __restrict__ b2,
                       const int* __restrict__ dst) {
    int idx = blockIdx.x * blockDim.x + threadIdx.x;
    if (idx < MLPN) {
        int l = idx / (EE * KH);
        int rem = idx - l * (EE * KH);
        int e = rem >> 5, k = rem & 31;
        float acc = b1[l * KH + k];
#pragma unroll
        for (int d = 0; d < 4; d++) acc += ea[e * 4 + d] * w1[l * 128 + d * KH + k];
        g_r[idx] = fmaxf(acc, 0.0f);
        return;
    }
    int t = idx - MLPN;
    if (t < BTOT) {
        int l = t / (H * KA);
        int rem = t - l * (H * KA);
        int o = rem / KA, c = rem - o * KA;
        float S;
        if (c < 2048) S = w2[l * 131072 + (c >> 6) * 4096 + (c & 63) * 64 + o];
        else if (c < 2112) S = b2[l * 4096 + (c - 2048) * 64 + o];
        else if (c < 2176) S = rw[l * 4096 + (c - 2112) * 64 + o];
        else S = rw[l * 4096 + (c - 2176) * 64 + o];
        g_B[t] = __float2half_rn(S);
        return;
    }
    int e = t - BTOT;
    if (e < EE) atomicAdd(&g_ddeg[dst[e]], 1);
}
// single-kernel CSR build (by dst): offsets -> grid barrier -> fill
__global__ __launch_bounds__(256) void k_csr(const int* __restrict__ dst) {
    int base = blockIdx.x * blockDim.x + threadIdx.x;
    for (int i = base; i < NN; i += CSRBLKS * 256) {
        int d = g_ddeg[i];
        int pos = (d > 0) ? atomicAdd(&g_total, d) : 0;
        g_soff[i] = pos;
        g_cursor[i] = pos;
        g_invdeg[i] = 1.0f / fmaxf((float)d, 1.0f);
    }
    gridbar(&g_done[2], CSRBLKS);
    for (int e = base; e < EE; e += CSRBLKS * 256) {
        int pos = atomicAdd(&g_cursor[dst[e]], 1);
        g_csr[pos] = e;
    }
}

// ===================== S-build: warp per dst, S/T in registers, no atomics =====================
// lane owns cols i = {2*lane, 2*lane+1}; S[k][i] accumulated over in-edges.
__global__ __launch_bounds__(256) void k_sbuild(const int* __restrict__ src, int layer) {
    int d = blockIdx.x * 8 + (threadIdx.x >> 5);
    int lane = threadIdx.x & 31;
    if (d >= NN) return;
    int cnt = g_ddeg[d];
    int beg = g_soff[d];
    float invd = g_invdeg[d];
    float Sk0[32], Sk1[32];
#pragma unroll
    for (int k = 0; k < 32; k++) { Sk0[k] = 0.0f; Sk1[k] = 0.0f; }
    float Tx = 0.0f, Ty = 0.0f;
    const float* rbase = g_r + (size_t)layer * EE * KH;
    for (int p = beg; p < beg + cnt; p++) {
        int e = g_csr[p];
        int s = src[e];
        float rk = rbase[e * KH + lane];
        float2 hv = *(const float2*)(g_hf + s * H + 2 * lane);
        Tx += hv.x;
        Ty += hv.y;
#pragma unroll
        for (int k = 0; k < 32; k++) {
            float rv = __shfl_sync(0xffffffffu, rk, k);
            Sk0[k] += rv * hv.x;
            Sk1[k] += rv * hv.y;
        }
    }
    __half* arow = g_A + (size_t)d * KA;
#pragma unroll
    for (int k = 0; k < 32; k++)
        *(__half2*)(arow + k * 64 + 2 * lane) =
            __floats2half2_rn(invd * Sk0[k], invd * Sk1[k]);
    *(__half2*)(arow + 2048 + 2 * lane) = __floats2half2_rn(invd * Tx, invd * Ty);
}

// ===================== GEMM: h_pre[10240,64] = A[10240,2240] @ B^T; 64x64 blocks =====================
__device__ __forceinline__ void mma_f16(float* c, const uint32_t* a, const uint32_t* b) {
    asm volatile(
        "mma.sync.aligned.m16n8k16.row.col.f32.f16.f16.f32 "
        "{%0,%1,%2,%3}, {%4,%5,%6,%7}, {%8,%9}, {%0,%1,%2,%3};"
        : "+f"(c[0]), "+f"(c[1]), "+f"(c[2]), "+f"(c[3])
        : "r"(a[0]), "r"(a[1]), "r"(a[2]), "r"(a[3]), "r"(b[0]), "r"(b[1]));
}
__device__ __forceinline__ void ldmx4(uint32_t* r, uint32_t addr) {
    asm volatile("ldmatrix.sync.aligned.m8n8.x4.shared.b16 {%0,%1,%2,%3}, [%4];"
                 : "=r"(r[0]), "=r"(r[1]), "=r"(r[2]), "=r"(r[3]) : "r"(addr));
}
__device__ __forceinline__ void cp16(uint32_t sdst, const void* gsrc) {
    asm volatile("cp.async.ca.shared.global [%0], [%1], 16;" :: "r"(sdst), "l"(gsrc));
}
#define CPCOMMIT() asm volatile("cp.async.commit_group;" ::: "memory")
#define CPWAIT1() asm volatile("cp.async.wait_group 1;" ::: "memory")
#define CPWAIT0() asm volatile("cp.async.wait_group 0;" ::: "memory")

#define CH 16               // K per chunk -> 140 chunks
#define NCHUNK (KA / CH)
#define SST 24              // smem row stride (halves) = 48B; cp.async-aligned
#define STG (128 * SST)     // per stage: 64 A rows + 64 B rows

__global__ __launch_bounds__(128) void k_gemm(int layer) {
    __shared__ __half sm[3][STG];   // 18432 B
    int tid = threadIdx.x;
    int lane = tid & 31, w = tid >> 5;
    int wm = w >> 1, wn = w & 1;    // 2(M) x 2(N) warps, 32x32 each
    int g = lane >> 2, tc = lane & 3;
    int n0 = blockIdx.x * 64;
    const __half* Bg = g_B + (size_t)layer * H * KA;

    // copy: thread t -> row t (A if <64 else B), two 16B pieces
    const __half* gsrc = (tid < 64) ? g_A + (size_t)(n0 + tid) * KA
                                    : Bg + (size_t)(tid - 64) * KA;
    uint32_t sdst = smem_u32(&sm[0][tid * SST]);
#define ISSUE(c, st) do {                                                  \
        uint32_t o = (uint32_t)(st) * (STG * 2);                           \
        cp16(sdst + o, gsrc + (c) * CH);                                   \
        cp16(sdst + o + 16, gsrc + (c) * CH + 8);                          \
    } while (0)

    int arow = (lane & 7) + ((lane >> 3) & 1) * 8;
    int acol = ((lane >> 4) & 1) * 8;
    int brow = (lane & 7) + ((lane >> 4) & 1) * 8;
    int bcol = ((lane >> 3) & 1) * 8;
    uint32_t aAddr[2], bAddr[2];
#pragma unroll
    for (int mi = 0; mi < 2; mi++)
        aAddr[mi] = smem_u32(&sm[0][(wm * 32 + mi * 16 + arow) * SST + acol]);
#pragma unroll
    for (int p = 0; p < 2; p++)
        bAddr[p] = smem_u32(&sm[0][(64 + wn * 32 + p * 16 + brow) * SST + bcol]);

    ISSUE(0, 0); CPCOMMIT();
    ISSUE(1, 1); CPCOMMIT();

    float acc[2][4][4] = {};
    int st = 0, isw = 2;
    for (int c = 0; c < NCHUNK; c++) {
        if (c < NCHUNK - 1) CPWAIT1(); else CPWAIT0();
        __syncthreads();
        uint32_t so = (uint32_t)(st * (STG * 2));
        uint32_t af[2][4], bq[2][4];
#pragma unroll
        for (int mi = 0; mi < 2; mi++) ldmx4(af[mi], aAddr[mi] + so);
#pragma unroll
        for (int p = 0; p < 2; p++) ldmx4(bq[p], bAddr[p] + so);
        if (c + 2 < NCHUNK) { ISSUE(c + 2, isw); CPCOMMIT(); }
#pragma unroll
        for (int mi = 0; mi < 2; mi++)
#pragma unroll
            for (int ni = 0; ni < 4; ni++)
                mma_f16(acc[mi][ni], af[mi], &bq[ni >> 1][(ni & 1) * 2]);
        st = (st == 2) ? 0 : st + 1;
        isw = (isw == 2) ? 0 : isw + 1;
    }
    // epilogue: h_pre fp32 direct
#pragma unroll
    for (int mi = 0; mi < 2; mi++) {
        int row0 = n0 + wm * 32 + mi * 16 + g;
#pragma unroll
        for (int ni = 0; ni < 4; ni++) {
            int col = wn * 32 + ni * 8 + tc * 2;
            *(float2*)(g_hp + (size_t)row0 * H + col) =
                make_float2(acc[mi][ni][0], acc[mi][ni][1]);
            *(float2*)(g_hp + (size_t)(row0 + 8) * H + col) =
                make_float2(acc[mi][ni][2], acc[mi][ni][3]);
        }
    }
#undef ISSUE
}

// ===================== fused norm (single-wave coop) =====================
__global__ __launch_bounds__(256) void k_norm(int l, float* __restrict__ out,
                                              const float* __restrict__ rb,
                                              const float* __restrict__ gw,
                                              const float* __restrict__ gb,
                                              const float* __restrict__ gms) {
    __shared__ float rs[256], rs2[256];
    int tid = threadIdx.x;
    int o = tid & 63, g = tid >> 6;
    int nbase = blockIdx.x * 80;
    float vloc[20];
    float s = 0.0f, s2 = 0.0f;
#pragma unroll
    for (int j = 0; j < 20; j++) {
        int n = nbase + j * 4 + g;
        float v = g_hp[n * H + o] + rb[o];
        vloc[j] = v;
        s += v;
        s2 += v * v;
    }
    rs[tid] = s;
    rs2[tid] = s2;
    __syncthreads();
    if (tid < 64) {
        float t = rs[tid] + rs[tid + 64] + rs[tid + 128] + rs[tid + 192];
        float t2 = rs2[tid] + rs2[tid + 64] + rs2[tid + 128] + rs2[tid + 192];
        atomicAdd(&g_colsum[l][tid], t);
        atomicAdd(&g_colsumsq[l][tid], t2);
        __threadfence();
    }
    __syncthreads();
    if (tid == 0) {
        atomicAdd(&g_done[l], 1);
        while (atomicAdd(&g_done[l], 0) < NORMBLKS) {}
    }
    __syncthreads();
    volatile float* cs = g_colsum[l];
    volatile float* cs2 = g_colsumsq[l];
    float mean = cs[o] * (1.0f / NN);
    float ex2 = cs2[o] * (1.0f / NN);
    float ms = gms[o];
    float var = ex2 - (2.0f * ms - ms * ms) * mean * mean;
    float a = gw[o] * rsqrtf(var + GEPS);
    float cc = gb[o] - a * ms * mean;
#pragma unroll
    for (int j = 0; j < 20; j++) {
        int n = nbase + j * 4 + g;
        float v = a * vloc[j] + cc;
        if (l == 0) {
            v = (v > 0.0f) ? v : 0.2f * v;
            g_hf[n * H + o] = v;
            __half hi = __float2half_rn(v);
            __half lo = __float2half_rn(v - __half2float(hi));
            g_A[(size_t)n * KA + 2112 + o] = hi;
            g_A[(size_t)n * KA + 2176 + o] = lo;
        } else {
            out[n * H + o] = v;
        }
    }
}

// ===================== launch =====================
extern "C" void kernel_launch(void* const* d_in, const int* in_sizes, int n_in,
                              void* d_out, int out_size) {
    const float* x      = (const float*)d_in[0];
    const int*   ei     = (const int*)d_in[1];
    const float* ea     = (const float*)d_in[2];
    const float* proj_w = (const float*)d_in[3];
    const float* proj_b = (const float*)d_in[4];
    const float* enn_w1 = (const float*)d_in[5];
    const float* enn_b1 = (const float*)d_in[6];
    const float* enn_w2 = (const float*)d_in[7];
    const float* enn_b2 = (const float*)d_in[8];
    const float* root_w = (const float*)d_in[9];
    const float* root_b = (const float*)d_in[10];
    const float* gn_w   = (const float*)d_in[11];
    const float* gn_b   = (const float*)d_in[12];
    const float* gn_ms  = (const float*)d_in[13];
    const int* src = ei;
    const int* dst = ei + EE;

    // launch #4 (= ncu capture slot) is k_sbuild layer 0
    k_proj<<<(NN * H + 255) / 256, 256>>>(x, proj_w, proj_b);
    k_prep<<<(PREPTOT + 255) / 256, 256>>>(ea, enn_w1, enn_b1, enn_w2, root_w, enn_b2,
                                           dst);
    k_csr<<<CSRBLKS, 256>>>(dst);
    k_sbuild<<<(NN + 7) / 8, 256>>>(src, 0);
    k_gemm<<<MPAD / 64, 128>>>(0);
    k_norm<<<NORMBLKS, 256>>>(0, (float*)d_out, root_b, gn_w, gn_b, gn_ms);
    k_sbuild<<<(NN + 7) / 8, 256>>>(src, 1);
    k_gemm<<<MPAD / 64, 128>>>(1);
    k_norm<<<NORMBLKS, 256>>>(1, (float*)d_out, root_b + H, gn_w + H, gn_b + H, gn_ms + H);
}

// round 14
// speedup vs baseline: 1.0182x; 1.0182x over previous
#include <cuda_runtime.h>
#include <cuda_fp16.h>
#include <cstdint>

#define NN 10000
#define MPAD 10240           // 160 * 64
#define EE 50000
#define IND 8
#define H 64
#define KH 32
#define KA 2240              // A cols: S(2048) | T(64) | h_hi(64) | h_lo(64)
#define GEPS 1e-5f
#define NORMBLKS 125         // 125 * 80 = 10000, single wave
#define CSRBLKS 125

// ===================== device scratch =====================
__device__ float g_r[2 * EE * KH];
__device__ float g_hf[NN * H];                      // fp32 node features
__device__ __half g_A[(size_t)MPAD * KA];           // GEMM A (45.9 MB)
__device__ __half g_B[2 * H * KA];                  // per-layer B as [o][c]
__device__ float g_hp[MPAD * H];                    // GEMM out: h_pre (pre-bias)
__device__ int g_ddeg[NN];
__device__ int g_soff[NN], g_cursor[NN], g_csr[EE];
__device__ int g_total;
__device__ int g_done[3];                           // [0],[1]=norm layers, [2]=csr
__device__ float g_invdeg[NN];
__device__ float g_colsum[2][H], g_colsumsq[2][H];

__device__ __forceinline__ uint32_t smem_u32(const void* p) {
    uint32_t a;
    asm("{ .reg .u64 t; cvta.to.shared.u64 t, %1; cvt.u32.u64 %0, t; }" : "=r"(a) : "l"(p));
    return a;
}
__device__ __forceinline__ void gridbar(int* ctr, int target) {
    __threadfence();
    __syncthreads();
    if (threadIdx.x == 0) {
        atomicAdd(ctr, 1);
        while (atomicAdd(ctr, 0) < target) {}
    }
    __syncthreads();
}

// ===================== setup kernels =====================
// h = x@proj_w+proj_b -> g_hf + g_A h-cols (hi/lo); zero counters
__global__ void k_proj(const float* __restrict__ x, const float* __restrict__ w,
                       const float* __restrict__ b) {
    int idx = blockIdx.x * blockDim.x + threadIdx.x;
    if (idx >= NN * H) return;
    if (idx < NN) g_ddeg[idx] = 0;
    if (idx < H) {
        g_colsum[0][idx] = 0.0f; g_colsumsq[0][idx] = 0.0f;
        g_colsum[1][idx] = 0.0f; g_colsumsq[1][idx] = 0.0f;
    }
    if (idx == 0) { g_total = 0; g_done[0] = 0; g_done[1] = 0; g_done[2] = 0; }
    int n = idx >> 6, o = idx & 63;
    float v = b[o];
#pragma unroll
    for (int i = 0; i < IND; i++) v += x[n * IND + i] * w[i * H + o];
    g_hf[idx] = v;
    __half hi = __float2half_rn(v);
    __half lo = __float2half_rn(v - __half2float(hi));
    g_A[(size_t)n * KA + 2112 + o] = hi;
    g_A[(size_t)n * KA + 2176 + o] = lo;
}
// merged: edge-MLP (both layers) + B build (both layers) + dst-degree count
#define MLPN (2 * EE * KH)
#define BTOT (2 * H * KA)
#define PREPTOT (MLPN + BTOT + EE)
__global__ void k_prep(const float* __restrict__ ea, const float* __restrict__ w1,
                       const float* __restrict__ b1, const float* __restrict__ w2,
                       const float* __restrict__ rw, const float* __restrict__ b2,
                       const int* __restrict__ dst) {
    int idx = blockIdx.x * blockDim.x + threadIdx.x;
    if (idx < MLPN) {
        int l = idx / (EE * KH);
        int rem = idx - l * (EE * KH);
        int e = rem >> 5, k = rem & 31;
        float acc = b1[l * KH + k];
#pragma unroll
        for (int d = 0; d < 4; d++) acc += ea[e * 4 + d] * w1[l * 128 + d * KH + k];
        g_r[idx] = fmaxf(acc, 0.0f);
        return;
    }
    int t = idx - MLPN;
    if (t < BTOT) {
        int l = t / (H * KA);
        int rem = t - l * (H * KA);
        int o = rem / KA, c = rem - o * KA;
        float S;
        if (c < 2048) S = w2[l * 131072 + (c >> 6) * 4096 + (c & 63) * 64 + o];
        else if (c < 2112) S = b2[l * 4096 + (c - 2048) * 64 + o];
        else if (c < 2176) S = rw[l * 4096 + (c - 2112) * 64 + o];
        else S = rw[l * 4096 + (c - 2176) * 64 + o];
        g_B[t] = __float2half_rn(S);
        return;
    }
    int e = t - BTOT;
    if (e < EE) atomicAdd(&g_ddeg[dst[e]], 1);
}
// single-kernel CSR build (by dst): offsets -> grid barrier -> fill
__global__ __launch_bounds__(256) void k_csr(const int* __restrict__ dst) {
    int base = blockIdx.x * blockDim.x + threadIdx.x;
    for (int i = base; i < NN; i += CSRBLKS * 256) {
        int d = g_ddeg[i];
        int pos = (d > 0) ? atomicAdd(&g_total, d) : 0;
        g_soff[i] = pos;
        g_cursor[i] = pos;
        g_invdeg[i] = 1.0f / fmaxf((float)d, 1.0f);
    }
    gridbar(&g_done[2], CSRBLKS);
    for (int e = base; e < EE; e += CSRBLKS * 256) {
        int pos = atomicAdd(&g_cursor[dst[e]], 1);
        g_csr[pos] = e;
    }
}

// ===================== S-build: 4 warps per dst (8 k's each), no atomics =====================
// lane owns cols i = {2*lane, 2*lane+1}; warp q handles k in [8q, 8q+8)
__global__ __launch_bounds__(256) void k_sbuild(const int* __restrict__ src, int layer) {
    int wid = threadIdx.x >> 5;            // 0..7
    int d = blockIdx.x * 2 + (wid >> 2);
    int q = wid & 3;
    int lane = threadIdx.x & 31;
    if (d >= NN) return;
    int cnt = g_ddeg[d];
    int beg = g_soff[d];
    float invd = g_invdeg[d];
    float S0[8], S1[8];
#pragma unroll
    for (int k = 0; k < 8; k++) { S0[k] = 0.0f; S1[k] = 0.0f; }
    float Tx = 0.0f, Ty = 0.0f;
    const float* rbase = g_r + (size_t)layer * EE * KH + q * 8;
    for (int p = beg; p < beg + cnt; p++) {
        int e = g_csr[p];
        int s = src[e];
        float rk = rbase[e * KH + (lane & 7)];
        float2 hv = *(const float2*)(g_hf + s * H + 2 * lane);
        Tx += hv.x;
        Ty += hv.y;
#pragma unroll
        for (int kk = 0; kk < 8; kk++) {
            float rv = __shfl_sync(0xffffffffu, rk, kk);
            S0[kk] += rv * hv.x;
            S1[kk] += rv * hv.y;
        }
    }
    __half* arow = g_A + (size_t)d * KA;
#pragma unroll
    for (int kk = 0; kk < 8; kk++)
        *(__half2*)(arow + (q * 8 + kk) * 64 + 2 * lane) =
            __floats2half2_rn(invd * S0[kk], invd * S1[kk]);
    if (q == 0)
        *(__half2*)(arow + 2048 + 2 * lane) = __floats2half2_rn(invd * Tx, invd * Ty);
}

// ===================== GEMM: h_pre[10240,64] = A[10240,2240] @ B^T; 64x64 blocks =====================
__device__ __forceinline__ void mma_f16(float* c, const uint32_t* a, const uint32_t* b) {
    asm volatile(
        "mma.sync.aligned.m16n8k16.row.col.f32.f16.f16.f32 "
        "{%0,%1,%2,%3}, {%4,%5,%6,%7}, {%8,%9}, {%0,%1,%2,%3};"
        : "+f"(c[0]), "+f"(c[1]), "+f"(c[2]), "+f"(c[3])
        : "r"(a[0]), "r"(a[1]), "r"(a[2]), "r"(a[3]), "r"(b[0]), "r"(b[1]));
}
__device__ __forceinline__ void ldmx4(uint32_t* r, uint32_t addr) {
    asm volatile("ldmatrix.sync.aligned.m8n8.x4.shared.b16 {%0,%1,%2,%3}, [%4];"
                 : "=r"(r[0]), "=r"(r[1]), "=r"(r[2]), "=r"(r[3]) : "r"(addr));
}
__device__ __forceinline__ void cp16(uint32_t sdst, const void* gsrc) {
    asm volatile("cp.async.ca.shared.global [%0], [%1], 16;" :: "r"(sdst), "l"(gsrc));
}
#define CPCOMMIT() asm volatile("cp.async.commit_group;" ::: "memory")
#define CPWAIT1() asm volatile("cp.async.wait_group 1;" ::: "memory")
#define CPWAIT0() asm volatile("cp.async.wait_group 0;" ::: "memory")

#define CH 16               // K per chunk -> 140 chunks
#define NCHUNK (KA / CH)
#define SST 24              // smem row stride (halves) = 48B; cp.async-aligned
#define STG (128 * SST)     // per stage: 64 A rows + 64 B rows

__global__ __launch_bounds__(128) void k_gemm(int layer) {
    __shared__ __half sm[3][STG];   // 18432 B
    int tid = threadIdx.x;
    int lane = tid & 31, w = tid >> 5;
    int wm = w >> 1, wn = w & 1;    // 2(M) x 2(N) warps, 32x32 each
    int g = lane >> 2, tc = lane & 3;
    int n0 = blockIdx.x * 64;
    const __half* Bg = g_B + (size_t)layer * H * KA;

    const __half* gsrc = (tid < 64) ? g_A + (size_t)(n0 + tid) * KA
                                    : Bg + (size_t)(tid - 64) * KA;
    uint32_t sdst = smem_u32(&sm[0][tid * SST]);
#define ISSUE(c, st) do {                                                  \
        uint32_t o = (uint32_t)(st) * (STG * 2);                           \
        cp16(sdst + o, gsrc + (c) * CH);                                   \
        cp16(sdst + o + 16, gsrc + (c) * CH + 8);                          \
    } while (0)

    int arow = (lane & 7) + ((lane >> 3) & 1) * 8;
    int acol = ((lane >> 4) & 1) * 8;
    int brow = (lane & 7) + ((lane >> 4) & 1) * 8;
    int bcol = ((lane >> 3) & 1) * 8;
    uint32_t aAddr[2], bAddr[2];
#pragma unroll
    for (int mi = 0; mi < 2; mi++)
        aAddr[mi] = smem_u32(&sm[0][(wm * 32 + mi * 16 + arow) * SST + acol]);
#pragma unroll
    for (int p = 0; p < 2; p++)
        bAddr[p] = smem_u32(&sm[0][(64 + wn * 32 + p * 16 + brow) * SST + bcol]);

    ISSUE(0, 0); CPCOMMIT();
    ISSUE(1, 1); CPCOMMIT();

    float acc[2][4][4] = {};
    int st = 0, isw = 2;
    for (int c = 0; c < NCHUNK; c++) {
        if (c < NCHUNK - 1) CPWAIT1(); else CPWAIT0();
        __syncthreads();
        uint32_t so = (uint32_t)(st * (STG * 2));
        uint32_t af[2][4], bq[2][4];
#pragma unroll
        for (int mi = 0; mi < 2; mi++) ldmx4(af[mi], aAddr[mi] + so);
#pragma unroll
        for (int p = 0; p < 2; p++) ldmx4(bq[p], bAddr[p] + so);
        if (c + 2 < NCHUNK) { ISSUE(c + 2, isw); CPCOMMIT(); }
#pragma unroll
        for (int mi = 0; mi < 2; mi++)
#pragma unroll
            for (int ni = 0; ni < 4; ni++)
                mma_f16(acc[mi][ni], af[mi], &bq[ni >> 1][(ni & 1) * 2]);
        st = (st == 2) ? 0 : st + 1;
        isw = (isw == 2) ? 0 : isw + 1;
    }
#pragma unroll
    for (int mi = 0; mi < 2; mi++) {
        int row0 = n0 + wm * 32 + mi * 16 + g;
#pragma unroll
        for (int ni = 0; ni < 4; ni++) {
            int col = wn * 32 + ni * 8 + tc * 2;
            *(float2*)(g_hp + (size_t)row0 * H + col) =
                make_float2(acc[mi][ni][0], acc[mi][ni][1]);
            *(float2*)(g_hp + (size_t)(row0 + 8) * H + col) =
                make_float2(acc[mi][ni][2], acc[mi][ni][3]);
        }
    }
#undef ISSUE
}

// ===================== fused norm (single-wave coop) =====================
__global__ __launch_bounds__(256) void k_norm(int l, float* __restrict__ out,
                                              const float* __restrict__ rb,
                                              const float* __restrict__ gw,
                                              const float* __restrict__ gb,
                                              const float* __restrict__ gms) {
    __shared__ float rs[256], rs2[256];
    int tid = threadIdx.x;
    int o = tid & 63, g = tid >> 6;
    int nbase = blockIdx.x * 80;
    float vloc[20];
    float s = 0.0f, s2 = 0.0f;
#pragma unroll
    for (int j = 0; j < 20; j++) {
        int n = nbase + j * 4 + g;
        float v = g_hp[n * H + o] + rb[o];
        vloc[j] = v;
        s += v;
        s2 += v * v;
    }
    rs[tid] = s;
    rs2[tid] = s2;
    __syncthreads();
    if (tid < 64) {
        float t = rs[tid] + rs[tid + 64] + rs[tid + 128] + rs[tid + 192];
        float t2 = rs2[tid] + rs2[tid + 64] + rs2[tid + 128] + rs2[tid + 192];
        atomicAdd(&g_colsum[l][tid], t);
        atomicAdd(&g_colsumsq[l][tid], t2);
        __threadfence();
    }
    __syncthreads();
    if (tid == 0) {
        atomicAdd(&g_done[l], 1);
        while (atomicAdd(&g_done[l], 0) < NORMBLKS) {}
    }
    __syncthreads();
    volatile float* cs = g_colsum[l];
    volatile float* cs2 = g_colsumsq[l];
    float mean = cs[o] * (1.0f / NN);
    float ex2 = cs2[o] * (1.0f / NN);
    float ms = gms[o];
    float var = ex2 - (2.0f * ms - ms * ms) * mean * mean;
    float a = gw[o] * rsqrtf(var + GEPS);
    float cc = gb[o] - a * ms * mean;
#pragma unroll
    for (int j = 0; j < 20; j++) {
        int n = nbase + j * 4 + g;
        float v = a * vloc[j] + cc;
        if (l == 0) {
            v = (v > 0.0f) ? v : 0.2f * v;
            g_hf[n * H + o] = v;
            __half hi = __float2half_rn(v);
            __half lo = __float2half_rn(v - __half2float(hi));
            g_A[(size_t)n * KA + 2112 + o] = hi;
            g_A[(size_t)n * KA + 2176 + o] = lo;
        } else {
            out[n * H + o] = v;
        }
    }
}

// ===================== launch =====================
extern "C" void kernel_launch(void* const* d_in, const int* in_sizes, int n_in,
                              void* d_out, int out_size) {
    const float* x      = (const float*)d_in[0];
    const int*   ei     = (const int*)d_in[1];
    const float* ea     = (const float*)d_in[2];
    const float* proj_w = (const float*)d_in[3];
    const float* proj_b = (const float*)d_in[4];
    const float* enn_w1 = (const float*)d_in[5];
    const float* enn_b1 = (const float*)d_in[6];
    const float* enn_w2 = (const float*)d_in[7];
    const float* enn_b2 = (const float*)d_in[8];
    const float* root_w = (const float*)d_in[9];
    const float* root_b = (const float*)d_in[10];
    const float* gn_w   = (const float*)d_in[11];
    const float* gn_b   = (const float*)d_in[12];
    const float* gn_ms  = (const float*)d_in[13];
    const int* src = ei;
    const int* dst = ei + EE;

    // launch #4 (= ncu capture slot) is k_sbuild layer 0
    k_proj<<<(NN * H + 255) / 256, 256>>>(x, proj_w, proj_b);
    k_prep<<<(PREPTOT + 255) / 256, 256>>>(ea, enn_w1, enn_b1, enn_w2, root_w, enn_b2,
                                           dst);
    k_csr<<<CSRBLKS, 256>>>(dst);
    k_sbuild<<<(NN + 1) / 2, 256>>>(src, 0);
    k_gemm<<<MPAD / 64, 128>>>(0);
    k_norm<<<NORMBLKS, 256>>>(0, (float*)d_out, root_b, gn_w, gn_b, gn_ms);
    k_sbuild<<<(NN + 1) / 2, 256>>>(src, 1);
    k_gemm<<<MPAD / 64, 128>>>(1);
    k_norm<<<NORMBLKS, 256>>>(1, (float*)d_out, root_b + H, gn_w + H, gn_b + H, gn_ms + H);
}

// round 15
// speedup vs baseline: 1.1317x; 1.1114x over previous
#include <cuda_runtime.h>
#include <cuda_fp16.h>
#include <cstdint>

#define NN 10000
#define MPAD 10240           // 160 * 64
#define EE 50000
#define IND 8
#define H 64
#define KH 32
#define KA 2240              // A cols: S(2048) | T(64) | h_hi(64) | h_lo(64)
#define KSL 560              // K per GEMM slice (4 slices)
#define GEPS 1e-5f
#define NORMBLKS 125         // 125 * 80 = 10000
#define GB 125               // k_graph blocks

// ===================== device scratch =====================
__device__ float g_r[2 * EE * KH];                  // edge MLP, CSR-sorted
__device__ float g_hf[NN * H];                      // fp32 node features
__device__ __half g_A[(size_t)MPAD * KA];           // GEMM A
__device__ __half g_B[2 * H * KA];                  // per-layer B as [o][c]
__device__ float g_hps[4][MPAD * H];                // per-K-slice GEMM outputs
__device__ int g_ddeg[NN];
__device__ int g_soff[NN], g_cursor[NN], g_srcs[EE];
__device__ int g_total;
__device__ int g_bctr[8], g_bgen[8];                // generational barriers (monotonic)
__device__ float g_invdeg[NN];
__device__ float g_colsum[2][H], g_colsumsq[2][H];

__device__ __forceinline__ uint32_t smem_u32(const void* p) {
    uint32_t a;
    asm("{ .reg .u64 t; cvta.to.shared.u64 t, %1; cvt.u32.u64 %0, t; }" : "=r"(a) : "l"(p));
    return a;
}
// replay-safe grid barrier: counter self-resets, generation is monotonic
__device__ __forceinline__ void gridbar(int i, int nblk) {
    __threadfence();
    __syncthreads();
    if (threadIdx.x == 0) {
        int g = atomicAdd(&g_bgen[i], 0);
        int v = atomicAdd(&g_bctr[i], 1);
        if (v == nblk - 1) {
            atomicExch(&g_bctr[i], 0);
            __threadfence();
            atomicAdd(&g_bgen[i], 1);
        } else {
            while (atomicAdd(&g_bgen[i], 0) == g) {}
        }
    }
    __syncthreads();
}

// ===================== fused graph setup: zero -> count -> offsets -> fill+edgeMLP =====================
__global__ __launch_bounds__(256) void k_graph(const int* __restrict__ src,
                                               const int* __restrict__ dst,
                                               const float* __restrict__ ea,
                                               const float* __restrict__ w1,
                                               const float* __restrict__ b1) {
    int t0 = blockIdx.x * 256 + threadIdx.x;
    const int STR = GB * 256;
    for (int i = t0; i < NN; i += STR) g_ddeg[i] = 0;
    if (t0 < H) {
        g_colsum[0][t0] = 0.0f; g_colsumsq[0][t0] = 0.0f;
        g_colsum[1][t0] = 0.0f; g_colsumsq[1][t0] = 0.0f;
    }
    if (t0 == 0) g_total = 0;
    gridbar(0, GB);
    for (int e = t0; e < EE; e += STR) atomicAdd(&g_ddeg[dst[e]], 1);
    gridbar(1, GB);
    for (int i = t0; i < NN; i += STR) {
        int d = *(volatile int*)&g_ddeg[i];
        int pos = (d > 0) ? atomicAdd(&g_total, d) : 0;
        g_soff[i] = pos;
        g_cursor[i] = pos;
        g_invdeg[i] = 1.0f / fmaxf((float)d, 1.0f);
    }
    gridbar(2, GB);
    for (int e = t0; e < EE; e += STR) {
        int pos = atomicAdd(&g_cursor[dst[e]], 1);
        g_srcs[pos] = src[e];
        float a0 = ea[e * 4], a1 = ea[e * 4 + 1], a2 = ea[e * 4 + 2], a3 = ea[e * 4 + 3];
#pragma unroll
        for (int l = 0; l < 2; l++) {
            float* rw_ = g_r + (size_t)l * EE * KH + (size_t)pos * KH;
            const float* W = w1 + l * 128;
            const float* B = b1 + l * KH;
#pragma unroll 8
            for (int k = 0; k < KH; k++) {
                float acc = B[k] + a0 * W[k] + a1 * W[32 + k] + a2 * W[64 + k] + a3 * W[96 + k];
                rw_[k] = fmaxf(acc, 0.0f);
            }
        }
    }
}

// ===================== proj: h = x@proj_w + proj_b -> g_hf + A h-cols =====================
__global__ void k_proj(const float* __restrict__ x, const float* __restrict__ w,
                       const float* __restrict__ b) {
    int idx = blockIdx.x * blockDim.x + threadIdx.x;
    if (idx >= NN * H) return;
    int n = idx >> 6, o = idx & 63;
    float v = b[o];
#pragma unroll
    for (int i = 0; i < IND; i++) v += x[n * IND + i] * w[i * H + o];
    g_hf[idx] = v;
    __half hi = __float2half_rn(v);
    __half lo = __float2half_rn(v - __half2float(hi));
    g_A[(size_t)n * KA + 2112 + o] = hi;
    g_A[(size_t)n * KA + 2176 + o] = lo;
}

// ===================== B build (both layers) =====================
#define BTOT (2 * H * KA)
__global__ void k_prepB(const float* __restrict__ w2, const float* __restrict__ rw,
                        const float* __restrict__ b2) {
    int t = blockIdx.x * blockDim.x + threadIdx.x;
    if (t >= BTOT) return;
    int l = t / (H * KA);
    int rem = t - l * (H * KA);
    int o = rem / KA, c = rem - o * KA;
    float S;
    if (c < 2048) S = w2[l * 131072 + (c >> 6) * 4096 + (c & 63) * 64 + o];
    else if (c < 2112) S = b2[l * 4096 + (c - 2048) * 64 + o];
    else if (c < 2176) S = rw[l * 4096 + (c - 2112) * 64 + o];
    else S = rw[l * 4096 + (c - 2176) * 64 + o];
    g_B[t] = __float2half_rn(S);
}

// ===================== S-build: 2 warps per dst, sorted inputs, 2-edge unroll =====================
__global__ __launch_bounds__(256) void k_sbuild(int layer) {
    int wid = threadIdx.x >> 5;            // 0..7
    int d = blockIdx.x * 4 + (wid >> 1);
    int q = wid & 1;
    int lane = threadIdx.x & 31;
    if (d >= NN) return;
    int cnt = g_ddeg[d];
    int beg = g_soff[d];
    float invd = g_invdeg[d];
    float S0[16], S1[16];
#pragma unroll
    for (int k = 0; k < 16; k++) { S0[k] = 0.0f; S1[k] = 0.0f; }
    float Tx = 0.0f, Ty = 0.0f;
    const float* rb = g_r + (size_t)layer * EE * KH + q * 16;
    int li = lane & 15;
    int p = beg, end = beg + cnt;
    for (; p + 2 <= end; p += 2) {
        int s0 = g_srcs[p], s1 = g_srcs[p + 1];
        float r0 = rb[(size_t)p * KH + li];
        float r1 = rb[(size_t)(p + 1) * KH + li];
        float2 h0 = *(const float2*)(g_hf + s0 * H + 2 * lane);
        float2 h1 = *(const float2*)(g_hf + s1 * H + 2 * lane);
        Tx += h0.x + h1.x;
        Ty += h0.y + h1.y;
#pragma unroll
        for (int kk = 0; kk < 16; kk++) {
            float rv0 = __shfl_sync(0xffffffffu, r0, kk);
            float rv1 = __shfl_sync(0xffffffffu, r1, kk);
            S0[kk] += rv0 * h0.x + rv1 * h1.x;
            S1[kk] += rv0 * h0.y + rv1 * h1.y;
        }
    }
    if (p < end) {
        int s0 = g_srcs[p];
        float r0 = rb[(size_t)p * KH + li];
        float2 h0 = *(const float2*)(g_hf + s0 * H + 2 * lane);
        Tx += h0.x;
        Ty += h0.y;
#pragma unroll
        for (int kk = 0; kk < 16; kk++) {
            float rv0 = __shfl_sync(0xffffffffu, r0, kk);
            S0[kk] += rv0 * h0.x;
            S1[kk] += rv0 * h0.y;
        }
    }
    __half* arow = g_A + (size_t)d * KA;
#pragma unroll
    for (int kk = 0; kk < 16; kk++)
        *(__half2*)(arow + (q * 16 + kk) * 64 + 2 * lane) =
            __floats2half2_rn(invd * S0[kk], invd * S1[kk]);
    if (q == 0)
        *(__half2*)(arow + 2048 + 2 * lane) = __floats2half2_rn(invd * Tx, invd * Ty);
}

// ===================== GEMM: 4-way K-split, 64x64 blocks, separate outputs =====================
__device__ __forceinline__ void mma_f16(float* c, const uint32_t* a, const uint32_t* b) {
    asm volatile(
        "mma.sync.aligned.m16n8k16.row.col.f32.f16.f16.f32 "
        "{%0,%1,%2,%3}, {%4,%5,%6,%7}, {%8,%9}, {%0,%1,%2,%3};"
        : "+f"(c[0]), "+f"(c[1]), "+f"(c[2]), "+f"(c[3])
        : "r"(a[0]), "r"(a[1]), "r"(a[2]), "r"(a[3]), "r"(b[0]), "r"(b[1]));
}
__device__ __forceinline__ void ldmx4(uint32_t* r, uint32_t addr) {
    asm volatile("ldmatrix.sync.aligned.m8n8.x4.shared.b16 {%0,%1,%2,%3}, [%4];"
                 : "=r"(r[0]), "=r"(r[1]), "=r"(r[2]), "=r"(r[3]) : "r"(addr));
}
__device__ __forceinline__ void cp16(uint32_t sdst, const void* gsrc) {
    asm volatile("cp.async.ca.shared.global [%0], [%1], 16;" :: "r"(sdst), "l"(gsrc));
}
#define CPCOMMIT() asm volatile("cp.async.commit_group;" ::: "memory")
#define CPWAIT1() asm volatile("cp.async.wait_group 1;" ::: "memory")
#define CPWAIT0() asm volatile("cp.async.wait_group 0;" ::: "memory")

#define CH 16               // K per chunk -> 35 chunks per slice
#define NCHUNK (KSL / CH)
#define SST 24              // smem row stride (halves) = 48B
#define STG (128 * SST)

__global__ __launch_bounds__(128) void k_gemm(int layer) {
    __shared__ __half sm[3][STG];   // 18432 B
    int tid = threadIdx.x;
    int lane = tid & 31, w = tid >> 5;
    int wm = w >> 1, wn = w & 1;    // 2(M) x 2(N) warps, 32x32 each
    int g = lane >> 2, tc = lane & 3;
    int n0 = blockIdx.x * 64;
    int ks = blockIdx.y;            // K slice 0..3
    const __half* Bg = g_B + (size_t)layer * H * KA + ks * KSL;
    const __half* Ag = g_A + ks * KSL;
    float* outp = g_hps[ks];

    const __half* gsrc = (tid < 64) ? Ag + (size_t)(n0 + tid) * KA
                                    : Bg + (size_t)(tid - 64) * KA;
    uint32_t sdst = smem_u32(&sm[0][tid * SST]);
#define ISSUE(c, st) do {                                                  \
        uint32_t o = (uint32_t)(st) * (STG * 2);                           \
        cp16(sdst + o, gsrc + (c) * CH);                                   \
        cp16(sdst + o + 16, gsrc + (c) * CH + 8);                          \
    } while (0)

    int arow = (lane & 7) + ((lane >> 3) & 1) * 8;
    int acol = ((lane >> 4) & 1) * 8;
    int brow = (lane & 7) + ((lane >> 4) & 1) * 8;
    int bcol = ((lane >> 3) & 1) * 8;
    uint32_t aAddr[2], bAddr[2];
#pragma unroll
    for (int mi = 0; mi < 2; mi++)
        aAddr[mi] = smem_u32(&sm[0][(wm * 32 + mi * 16 + arow) * SST + acol]);
#pragma unroll
    for (int p = 0; p < 2; p++)
        bAddr[p] = smem_u32(&sm[0][(64 + wn * 32 + p * 16 + brow) * SST + bcol]);

    ISSUE(0, 0); CPCOMMIT();
    ISSUE(1, 1); CPCOMMIT();

    float acc[2][4][4] = {};
    int st = 0, isw = 2;
    for (int c = 0; c < NCHUNK; c++) {
        if (c < NCHUNK - 1) CPWAIT1(); else CPWAIT0();
        __syncthreads();
        uint32_t so = (uint32_t)(st * (STG * 2));
        uint32_t af[2][4], bq[2][4];
#pragma unroll
        for (int mi = 0; mi < 2; mi++) ldmx4(af[mi], aAddr[mi] + so);
#pragma unroll
        for (int p = 0; p < 2; p++) ldmx4(bq[p], bAddr[p] + so);
        if (c + 2 < NCHUNK) { ISSUE(c + 2, isw); CPCOMMIT(); }
#pragma unroll
        for (int mi = 0; mi < 2; mi++)
#pragma unroll
            for (int ni = 0; ni < 4; ni++)
                mma_f16(acc[mi][ni], af[mi], &bq[ni >> 1][(ni & 1) * 2]);
        st = (st == 2) ? 0 : st + 1;
        isw = (isw == 2) ? 0 : isw + 1;
    }
#pragma unroll
    for (int mi = 0; mi < 2; mi++) {
        int row0 = n0 + wm * 32 + mi * 16 + g;
#pragma unroll
        for (int ni = 0; ni < 4; ni++) {
            int col = wn * 32 + ni * 8 + tc * 2;
            *(float2*)(outp + (size_t)row0 * H + col) =
                make_float2(acc[mi][ni][0], acc[mi][ni][1]);
            *(float2*)(outp + (size_t)(row0 + 8) * H + col) =
                make_float2(acc[mi][ni][2], acc[mi][ni][3]);
        }
    }
#undef ISSUE
}

// ===================== fused norm (single-wave coop, generational barrier) =====================
__global__ __launch_bounds__(256) void k_norm(int l, float* __restrict__ out,
                                              const float* __restrict__ rb,
                                              const float* __restrict__ gw,
                                              const float* __restrict__ gb,
                                              const float* __restrict__ gms) {
    __shared__ float rs[256], rs2[256];
    int tid = threadIdx.x;
    int o = tid & 63, g = tid >> 6;
    int nbase = blockIdx.x * 80;
    float vloc[20];
    float s = 0.0f, s2 = 0.0f;
#pragma unroll
    for (int j = 0; j < 20; j++) {
        int n = nbase + j * 4 + g;
        int idx = n * H + o;
        float v = g_hps[0][idx] + g_hps[1][idx] + g_hps[2][idx] + g_hps[3][idx] + rb[o];
        vloc[j] = v;
        s += v;
        s2 += v * v;
    }
    rs[tid] = s;
    rs2[tid] = s2;
    __syncthreads();
    if (tid < 64) {
        float t = rs[tid] + rs[tid + 64] + rs[tid + 128] + rs[tid + 192];
        float t2 = rs2[tid] + rs2[tid + 64] + rs2[tid + 128] + rs2[tid + 192];
        atomicAdd(&g_colsum[l][tid], t);
        atomicAdd(&g_colsumsq[l][tid], t2);
    }
    gridbar(3 + l, NORMBLKS);
    volatile float* cs = g_colsum[l];
    volatile float* cs2 = g_colsumsq[l];
    float mean = cs[o] * (1.0f / NN);
    float ex2 = cs2[o] * (1.0f / NN);
    float ms = gms[o];
    float var = ex2 - (2.0f * ms - ms * ms) * mean * mean;
    float a = gw[o] * rsqrtf(var + GEPS);
    float cc = gb[o] - a * ms * mean;
#pragma unroll
    for (int j = 0; j < 20; j++) {
        int n = nbase + j * 4 + g;
        float v = a * vloc[j] + cc;
        if (l == 0) {
            v = (v > 0.0f) ? v : 0.2f * v;
            g_hf[n * H + o] = v;
            __half hi = __float2half_rn(v);
            __half lo = __float2half_rn(v - __half2float(hi));
            g_A[(size_t)n * KA + 2112 + o] = hi;
            g_A[(size_t)n * KA + 2176 + o] = lo;
        } else {
            out[n * H + o] = v;
        }
    }
}

// ===================== launch =====================
extern "C" void kernel_launch(void* const* d_in, const int* in_sizes, int n_in,
                              void* d_out, int out_size) {
    const float* x      = (const float*)d_in[0];
    const int*   ei     = (const int*)d_in[1];
    const float* ea     = (const float*)d_in[2];
    const float* proj_w = (const float*)d_in[3];
    const float* proj_b = (const float*)d_in[4];
    const float* enn_w1 = (const float*)d_in[5];
    const float* enn_b1 = (const float*)d_in[6];
    const float* enn_w2 = (const float*)d_in[7];
    const float* enn_b2 = (const float*)d_in[8];
    const float* root_w = (const float*)d_in[9];
    const float* root_b = (const float*)d_in[10];
    const float* gn_w   = (const float*)d_in[11];
    const float* gn_b   = (const float*)d_in[12];
    const float* gn_ms  = (const float*)d_in[13];
    const int* src = ei;
    const int* dst = ei + EE;

    // launch #4 (= ncu capture slot) is k_sbuild layer 0
    k_graph<<<GB, 256>>>(src, dst, ea, enn_w1, enn_b1);
    k_proj<<<(NN * H + 255) / 256, 256>>>(x, proj_w, proj_b);
    k_prepB<<<(BTOT + 255) / 256, 256>>>(enn_w2, root_w, enn_b2);
    k_sbuild<<<(NN + 3) / 4, 256>>>(0);
    k_gemm<<<dim3(MPAD / 64, 4), 128>>>(0);
    k_norm<<<NORMBLKS, 256>>>(0, (float*)d_out, root_b, gn_w, gn_b, gn_ms);
    k_sbuild<<<(NN + 3) / 4, 256>>>(1);
    k_gemm<<<dim3(MPAD / 64, 4), 128>>>(1);
    k_norm<<<NORMBLKS, 256>>>(1, (float*)d_out, root_b + H, gn_w + H, gn_b + H, gn_ms + H);
}